// round 1
// baseline (speedup 1.0000x reference)
#include <cuda_runtime.h>

typedef unsigned int u32;
typedef unsigned long long u64;

#define N_PTS 32768
#define N_CLU 512
#define DIM   1024
#define NBATCH 16
#define NPB   2048   // points per batch
#define CHUNK 4096   // bitonic local chunk (32KB smem)

// ---------------- scratch (device globals; no allocation) ----------------
__device__ u64 g_sortbuf[N_PTS];
__device__ int g_val[N_PTS];
__device__ __align__(16) float g_cent[N_CLU * DIM];
__device__ float g_csq[N_CLU];
__device__ int g_idx[N_PTS];
__device__ __align__(16) float g_sums[N_CLU * DIM];
__device__ int g_counts[N_CLU];
__device__ int g_counts2[NBATCH * N_CLU];

// ---------------- Threefry-2x32 (matches jax._src.prng) ----------------
__host__ __device__ inline void tf2x32(u32 k0, u32 k1, u32 x0, u32 x1,
                                       u32& o0, u32& o1) {
    u32 ks2 = k0 ^ k1 ^ 0x1BD11BDAu;
    x0 += k0; x1 += k1;
#define TF_R(r) { x0 += x1; x1 = (x1 << (r)) | (x1 >> (32 - (r))); x1 ^= x0; }
    TF_R(13) TF_R(15) TF_R(26) TF_R(6)
    x0 += k1;  x1 += ks2 + 1u;
    TF_R(17) TF_R(29) TF_R(16) TF_R(24)
    x0 += ks2; x1 += k0 + 2u;
    TF_R(13) TF_R(15) TF_R(26) TF_R(6)
    x0 += k0;  x1 += k1 + 3u;
    TF_R(17) TF_R(29) TF_R(16) TF_R(24)
    x0 += k1;  x1 += ks2 + 4u;
    TF_R(13) TF_R(15) TF_R(26) TF_R(6)
    x0 += ks2; x1 += k0 + 5u;
#undef TF_R
    o0 = x0; o1 = x1;
}

// partitionable random_bits: bits[i] = lane0 ^ lane1 of T(subkey, (0, i))
__global__ void gen_keys_kernel(u32 sk0, u32 sk1) {
    int i = blockIdx.x * blockDim.x + threadIdx.x;
    if (i >= N_PTS) return;
    u32 a, b;
    tf2x32(sk0, sk1, 0u, (u32)i, a, b);
    g_sortbuf[i] = ((u64)(a ^ b) << 32) | (u32)i;
}

// ---------------- bitonic sort (stable via (key,pos) composite) ----------------
__global__ void sort_local(void) {
    __shared__ u64 s[CHUNK];
    int base = blockIdx.x * CHUNK;
    for (int t = threadIdx.x; t < CHUNK; t += blockDim.x) s[t] = g_sortbuf[base + t];
    __syncthreads();
    for (int k = 2; k <= CHUNK; k <<= 1) {
        for (int j = k >> 1; j > 0; j >>= 1) {
            for (int t = threadIdx.x; t < CHUNK / 2; t += blockDim.x) {
                int i = ((t & ~(j - 1)) << 1) | (t & (j - 1));
                int l = i | j;
                bool asc = (((base + i) & k) == 0);
                u64 x = s[i], y = s[l];
                if ((x > y) == asc) { s[i] = y; s[l] = x; }
            }
            __syncthreads();
        }
    }
    for (int t = threadIdx.x; t < CHUNK; t += blockDim.x) g_sortbuf[base + t] = s[t];
}

__global__ void sort_global(int k, int j) {
    int t = blockIdx.x * blockDim.x + threadIdx.x;   // < N_PTS/2
    int i = ((t & ~(j - 1)) << 1) | (t & (j - 1));
    int l = i | j;
    bool asc = ((i & k) == 0);
    u64 x = g_sortbuf[i], y = g_sortbuf[l];
    if ((x > y) == asc) { g_sortbuf[i] = y; g_sortbuf[l] = x; }
}

__global__ void sort_merge(int k) {
    __shared__ u64 s[CHUNK];
    int base = blockIdx.x * CHUNK;
    bool asc = ((base & k) == 0);   // k >= 2*CHUNK here, constant per block
    for (int t = threadIdx.x; t < CHUNK; t += blockDim.x) s[t] = g_sortbuf[base + t];
    __syncthreads();
    for (int j = CHUNK / 2; j > 0; j >>= 1) {
        for (int t = threadIdx.x; t < CHUNK / 2; t += blockDim.x) {
            int i = ((t & ~(j - 1)) << 1) | (t & (j - 1));
            int l = i | j;
            u64 x = s[i], y = s[l];
            if ((x > y) == asc) { s[i] = y; s[l] = x; }
        }
        __syncthreads();
    }
    for (int t = threadIdx.x; t < CHUNK; t += blockDim.x) g_sortbuf[base + t] = s[t];
}

__global__ void extract_val(void) {
    int i = blockIdx.x * blockDim.x + threadIdx.x;
    if (i < N_PTS) g_val[i] = (int)(g_sortbuf[i] & 0xFFFFFFFFu);
}

// centroids[c] = x_flat[perm[c]],  perm[c] = v1[ low32(sorted2[c]) ]
__global__ void gather_init(const float* __restrict__ X) {
    int c = blockIdx.x;                     // < 512
    int pos = (int)(g_sortbuf[c] & 0xFFFFFFFFu);
    int src = g_val[pos];
    const float4* s = (const float4*)&X[(size_t)src * DIM];
    float4* d = (float4*)&g_cent[(size_t)c * DIM];
    d[threadIdx.x] = s[threadIdx.x];        // 256 threads x float4 = 1024 floats
}

// ---------------- k-means iteration ----------------
__global__ void csq_kernel(void) {
    int c = blockIdx.x;
    const float* row = &g_cent[(size_t)c * DIM];
    float s = 0.f;
    for (int t = threadIdx.x; t < DIM; t += 256) { float v = row[t]; s += v * v; }
    __shared__ float red[256];
    red[threadIdx.x] = s; __syncthreads();
    for (int o = 128; o > 0; o >>= 1) {
        if (threadIdx.x < o) red[threadIdx.x] += red[threadIdx.x + o];
        __syncthreads();
    }
    if (threadIdx.x == 0) g_csq[c] = red[0];
}

// argmin_c ( csq[c] - 2 * x_p . cent_c )  -- 128x128x8 tiled fp32 GEMM + fused argmin
__global__ __launch_bounds__(256) void assign_kernel(const float* __restrict__ X) {
    __shared__ float Xs[8][128];
    __shared__ float Cs[8][128];
    __shared__ float rbest[128][16];
    __shared__ int   ridx[128][16];

    int row0 = blockIdx.x * 128;
    int tid = threadIdx.x;
    int tx = tid & 15, ty = tid >> 4;
    int lr = tid >> 1;             // load row 0..127
    int lk = (tid & 1) * 4;        // 0 or 4

    float best[8];
    int bidx[8];
#pragma unroll
    for (int i = 0; i < 8; i++) { best[i] = 3.4e38f; bidx[i] = 0; }

    for (int nt = 0; nt < 4; nt++) {
        int col0 = nt * 128;
        float acc[8][8];
#pragma unroll
        for (int i = 0; i < 8; i++)
#pragma unroll
            for (int j = 0; j < 8; j++) acc[i][j] = 0.f;

        for (int kt = 0; kt < DIM; kt += 8) {
            float4 xv = *(const float4*)&X[(size_t)(row0 + lr) * DIM + kt + lk];
            float4 cv = *(const float4*)&g_cent[(size_t)(col0 + lr) * DIM + kt + lk];
            __syncthreads();
            Xs[lk + 0][lr] = xv.x; Xs[lk + 1][lr] = xv.y;
            Xs[lk + 2][lr] = xv.z; Xs[lk + 3][lr] = xv.w;
            Cs[lk + 0][lr] = cv.x; Cs[lk + 1][lr] = cv.y;
            Cs[lk + 2][lr] = cv.z; Cs[lk + 3][lr] = cv.w;
            __syncthreads();
#pragma unroll
            for (int kk = 0; kk < 8; kk++) {
                float4 a0 = *(float4*)&Xs[kk][ty * 8];
                float4 a1 = *(float4*)&Xs[kk][ty * 8 + 4];
                float4 b0 = *(float4*)&Cs[kk][tx * 8];
                float4 b1 = *(float4*)&Cs[kk][tx * 8 + 4];
                float a[8] = {a0.x, a0.y, a0.z, a0.w, a1.x, a1.y, a1.z, a1.w};
                float b[8] = {b0.x, b0.y, b0.z, b0.w, b1.x, b1.y, b1.z, b1.w};
#pragma unroll
                for (int i = 0; i < 8; i++)
#pragma unroll
                    for (int j = 0; j < 8; j++) acc[i][j] += a[i] * b[j];
            }
        }
        // fused argmin epilogue (columns scanned ascending -> first-min tie-break)
#pragma unroll
        for (int j = 0; j < 8; j++) {
            int c = col0 + tx * 8 + j;
            float cs = g_csq[c];
#pragma unroll
            for (int i = 0; i < 8; i++) {
                float s = cs - 2.0f * acc[i][j];
                if (s < best[i]) { best[i] = s; bidx[i] = c; }
            }
        }
        __syncthreads();
    }
#pragma unroll
    for (int i = 0; i < 8; i++) {
        rbest[ty * 8 + i][tx] = best[i];
        ridx[ty * 8 + i][tx] = bidx[i];
    }
    __syncthreads();
    if (tid < 128) {
        float bv = rbest[tid][0]; int bi = ridx[tid][0];
#pragma unroll
        for (int t = 1; t < 16; t++) {
            float v = rbest[tid][t]; int c = ridx[tid][t];
            if (v < bv || (v == bv && c < bi)) { bv = v; bi = c; }
        }
        g_idx[row0 + tid] = bi;
    }
}

__global__ void zero_sums(void) {
    int t = blockIdx.x * blockDim.x + threadIdx.x;
    if (t < N_CLU * DIM) g_sums[t] = 0.f;
    if (t < N_CLU) g_counts[t] = 0;
}

__global__ void scatter_add(const float* __restrict__ X) {
    int p = blockIdx.x;
    int c = g_idx[p];
    const float4* src = (const float4*)&X[(size_t)p * DIM];
    float4* dst = (float4*)&g_sums[(size_t)c * DIM];
    atomicAdd(&dst[threadIdx.x], src[threadIdx.x]);   // 256 x float4
    if (threadIdx.x == 0) atomicAdd(&g_counts[c], 1);
}

__global__ void finalize_cent(void) {
    int c = blockIdx.x;
    int cnt = g_counts[c];
    float fc = (float)cnt;
    for (int k = threadIdx.x; k < DIM; k += 256)
        g_cent[(size_t)c * DIM + k] = (cnt > 0) ? g_sums[(size_t)c * DIM + k] / fc : 0.f;
}

// ---------------- final per-batch compression ----------------
__global__ void zero_out(float* __restrict__ out) {
    int t = blockIdx.x * blockDim.x + threadIdx.x;   // 8192*1024 threads
    out[t] = 0.f;
    if (t < NBATCH * N_CLU) g_counts2[t] = 0;
}

__global__ void scatter_out(const float* __restrict__ X, float* __restrict__ out) {
    int p = blockIdx.x;
    int b = p >> 11;                 // /2048
    int s = b * N_CLU + g_idx[p];
    const float4* src = (const float4*)&X[(size_t)p * DIM];
    float4* dst = (float4*)&out[(size_t)s * DIM];
    atomicAdd(&dst[threadIdx.x], src[threadIdx.x]);
    if (threadIdx.x == 0) atomicAdd(&g_counts2[s], 1);
}

__global__ void div_out(float* __restrict__ out) {
    int s = blockIdx.x;
    int cnt = g_counts2[s];
    if (cnt <= 0) return;            // stays zero (matches reference where())
    float fc = (float)cnt;
    for (int k = threadIdx.x; k < DIM; k += 256)
        out[(size_t)s * DIM + k] /= fc;
}

// ---------------- driver ----------------
static void run_full_sort() {
    sort_local<<<N_PTS / CHUNK, 512>>>();
    for (int k = 2 * CHUNK; k <= N_PTS; k <<= 1) {
        for (int j = k >> 1; j >= CHUNK; j >>= 1)
            sort_global<<<N_PTS / 2 / 256, 256>>>(k, j);
        sort_merge<<<N_PTS / CHUNK, 512>>>(k);
    }
}

extern "C" void kernel_launch(void* const* d_in, const int* in_sizes, int n_in,
                              void* d_out, int out_size) {
    (void)in_sizes; (void)n_in; (void)out_size;
    const float* X = (const float*)d_in[0];
    float* out = (float*)d_out;

    // jax.random.key(42) -> threefry key (0, 42)
    // partitionable split: keys_i = T(key, (0, i)); key,subkey = rows 0,1
    u32 K1a, K1b, S1a, S1b, S2a, S2b, t0, t1;
    tf2x32(0u, 42u, 0u, 0u, K1a, K1b);     // new key after round-1 split
    tf2x32(0u, 42u, 0u, 1u, S1a, S1b);     // round-1 subkey
    tf2x32(K1a, K1b, 0u, 1u, S2a, S2b);    // round-2 subkey
    tf2x32(K1a, K1b, 0u, 0u, t0, t1);      // (unused new key, keeps parity clear)
    (void)t0; (void)t1;

    // shuffle round 1: sort (bits1, i); values are arange -> low bits = value
    gen_keys_kernel<<<N_PTS / 256, 256>>>(S1a, S1b);
    run_full_sort();
    extract_val<<<N_PTS / 256, 256>>>();
    // shuffle round 2
    gen_keys_kernel<<<N_PTS / 256, 256>>>(S2a, S2b);
    run_full_sort();

    gather_init<<<N_CLU, 256>>>(X);

    for (int it = 0; it < 10; it++) {
        csq_kernel<<<N_CLU, 256>>>();
        assign_kernel<<<N_PTS / 128, 256>>>(X);
        zero_sums<<<(N_CLU * DIM) / 256, 256>>>();
        scatter_add<<<N_PTS, 256>>>(X);
        finalize_cent<<<N_CLU, 256>>>();
    }

    zero_out<<<(NBATCH * N_CLU * DIM) / 1024, 1024>>>(out);
    scatter_out<<<N_PTS, 256>>>(X, out);
    div_out<<<NBATCH * N_CLU, 256>>>(out);
}

// round 2
// speedup vs baseline: 1.0086x; 1.0086x over previous
#include <cuda_runtime.h>

typedef unsigned int u32;
typedef unsigned long long u64;

#define N_PTS 32768
#define N_CLU 512
#define DIM   1024
#define NBATCH 16
#define CHUNK 4096   // bitonic local chunk (32KB smem)

// ---------------- scratch (device globals; no allocation) ----------------
__device__ u64 g_sortbuf[N_PTS];
__device__ int g_val[N_PTS];
__device__ __align__(16) float g_cent[N_CLU * DIM];
__device__ float g_csq[N_CLU];
__device__ int g_idx[N_PTS];
__device__ __align__(16) float g_sums[N_CLU * DIM];
__device__ int g_counts[N_CLU];
__device__ int g_counts2[NBATCH * N_CLU];

// ---------------- packed fp32x2 helpers (Blackwell FFMA2) ----------------
__device__ __forceinline__ u64 pack2(float x, float y) {
    u32 xi = __float_as_uint(x), yi = __float_as_uint(y);
    u64 r;
    asm("mov.b64 %0, {%1,%2};" : "=l"(r) : "r"(xi), "r"(yi));
    return r;
}
__device__ __forceinline__ void unpack2(u64 v, float& x, float& y) {
    u32 xi, yi;
    asm("mov.b64 {%0,%1}, %2;" : "=r"(xi), "=r"(yi) : "l"(v));
    x = __uint_as_float(xi); y = __uint_as_float(yi);
}
__device__ __forceinline__ u64 swap_halves(u64 v) {
    u32 lo, hi;
    asm("mov.b64 {%0,%1}, %2;" : "=r"(lo), "=r"(hi) : "l"(v));
    u64 r;
    asm("mov.b64 %0, {%1,%2};" : "=l"(r) : "r"(hi), "r"(lo));
    return r;
}
__device__ __forceinline__ u64 fma2(u64 a, u64 b, u64 c) {
    u64 d;
    asm("fma.rn.f32x2 %0, %1, %2, %3;" : "=l"(d) : "l"(a), "l"(b), "l"(c));
    return d;
}

// ---------------- Threefry-2x32 (matches jax._src.prng) ----------------
__host__ __device__ inline void tf2x32(u32 k0, u32 k1, u32 x0, u32 x1,
                                       u32& o0, u32& o1) {
    u32 ks2 = k0 ^ k1 ^ 0x1BD11BDAu;
    x0 += k0; x1 += k1;
#define TF_R(r) { x0 += x1; x1 = (x1 << (r)) | (x1 >> (32 - (r))); x1 ^= x0; }
    TF_R(13) TF_R(15) TF_R(26) TF_R(6)
    x0 += k1;  x1 += ks2 + 1u;
    TF_R(17) TF_R(29) TF_R(16) TF_R(24)
    x0 += ks2; x1 += k0 + 2u;
    TF_R(13) TF_R(15) TF_R(26) TF_R(6)
    x0 += k0;  x1 += k1 + 3u;
    TF_R(17) TF_R(29) TF_R(16) TF_R(24)
    x0 += k1;  x1 += ks2 + 4u;
    TF_R(13) TF_R(15) TF_R(26) TF_R(6)
    x0 += ks2; x1 += k0 + 5u;
#undef TF_R
    o0 = x0; o1 = x1;
}

// partitionable random_bits: bits[i] = lane0 ^ lane1 of T(subkey, (0, i))
__global__ void gen_keys_kernel(u32 sk0, u32 sk1) {
    int i = blockIdx.x * blockDim.x + threadIdx.x;
    if (i >= N_PTS) return;
    u32 a, b;
    tf2x32(sk0, sk1, 0u, (u32)i, a, b);
    g_sortbuf[i] = ((u64)(a ^ b) << 32) | (u32)i;
}

// ---------------- bitonic sort (stable via (key,pos) composite) ----------------
__global__ void sort_local(void) {
    __shared__ u64 s[CHUNK];
    int base = blockIdx.x * CHUNK;
    for (int t = threadIdx.x; t < CHUNK; t += blockDim.x) s[t] = g_sortbuf[base + t];
    __syncthreads();
    for (int k = 2; k <= CHUNK; k <<= 1) {
        for (int j = k >> 1; j > 0; j >>= 1) {
            for (int t = threadIdx.x; t < CHUNK / 2; t += blockDim.x) {
                int i = ((t & ~(j - 1)) << 1) | (t & (j - 1));
                int l = i | j;
                bool asc = (((base + i) & k) == 0);
                u64 x = s[i], y = s[l];
                if ((x > y) == asc) { s[i] = y; s[l] = x; }
            }
            __syncthreads();
        }
    }
    for (int t = threadIdx.x; t < CHUNK; t += blockDim.x) g_sortbuf[base + t] = s[t];
}

__global__ void sort_global(int k, int j) {
    int t = blockIdx.x * blockDim.x + threadIdx.x;   // < N_PTS/2
    int i = ((t & ~(j - 1)) << 1) | (t & (j - 1));
    int l = i | j;
    bool asc = ((i & k) == 0);
    u64 x = g_sortbuf[i], y = g_sortbuf[l];
    if ((x > y) == asc) { g_sortbuf[i] = y; g_sortbuf[l] = x; }
}

__global__ void sort_merge(int k) {
    __shared__ u64 s[CHUNK];
    int base = blockIdx.x * CHUNK;
    bool asc = ((base & k) == 0);   // k >= 2*CHUNK here, constant per block
    for (int t = threadIdx.x; t < CHUNK; t += blockDim.x) s[t] = g_sortbuf[base + t];
    __syncthreads();
    for (int j = CHUNK / 2; j > 0; j >>= 1) {
        for (int t = threadIdx.x; t < CHUNK / 2; t += blockDim.x) {
            int i = ((t & ~(j - 1)) << 1) | (t & (j - 1));
            int l = i | j;
            u64 x = s[i], y = s[l];
            if ((x > y) == asc) { s[i] = y; s[l] = x; }
        }
        __syncthreads();
    }
    for (int t = threadIdx.x; t < CHUNK; t += blockDim.x) g_sortbuf[base + t] = s[t];
}

__global__ void extract_val(void) {
    int i = blockIdx.x * blockDim.x + threadIdx.x;
    if (i < N_PTS) g_val[i] = (int)(g_sortbuf[i] & 0xFFFFFFFFu);
}

// centroids[c] = x_flat[perm[c]],  perm[c] = v1[ low32(sorted2[c]) ]
__global__ void gather_init(const float* __restrict__ X) {
    int c = blockIdx.x;                     // < 512
    int pos = (int)(g_sortbuf[c] & 0xFFFFFFFFu);
    int src = g_val[pos];
    const float4* s = (const float4*)&X[(size_t)src * DIM];
    float4* d = (float4*)&g_cent[(size_t)c * DIM];
    d[threadIdx.x] = s[threadIdx.x];        // 256 threads x float4 = 1024 floats
}

// ---------------- k-means iteration ----------------
__global__ void csq_kernel(void) {
    int c = blockIdx.x;
    const float* row = &g_cent[(size_t)c * DIM];
    float s = 0.f;
    for (int t = threadIdx.x; t < DIM; t += 256) { float v = row[t]; s += v * v; }
    __shared__ float red[256];
    red[threadIdx.x] = s; __syncthreads();
    for (int o = 128; o > 0; o >>= 1) {
        if (threadIdx.x < o) red[threadIdx.x] += red[threadIdx.x + o];
        __syncthreads();
    }
    if (threadIdx.x == 0) g_csq[c] = red[0];
}

// argmin_c ( csq[c] - 2 * x_p . cent_c )
// 128x128x8 tiled GEMM on packed fp32x2 (FFMA2) + fused argmin.
// Per-(row,col) accumulation order identical to the scalar version ->
// bit-identical results.
__global__ __launch_bounds__(256) void assign_kernel(const float* __restrict__ X) {
    __shared__ float Xs[8][128];
    __shared__ float Cs[8][128];
    __shared__ float rbest[128][16];
    __shared__ int   ridx[128][16];

    int row0 = blockIdx.x * 128;
    int tid = threadIdx.x;
    int tx = tid & 15, ty = tid >> 4;
    int lr = tid >> 1;             // load row 0..127
    int lk = (tid & 1) * 4;        // 0 or 4

    float best[8];
    int bidx[8];
#pragma unroll
    for (int i = 0; i < 8; i++) { best[i] = 3.4e38f; bidx[i] = 0; }

    for (int nt = 0; nt < 4; nt++) {
        int col0 = nt * 128;
        // accD[i2][j2]: (a_{2i2}b_{2j2}, a_{2i2+1}b_{2j2+1})
        // accX[i2][j2]: (a_{2i2}b_{2j2+1}, a_{2i2+1}b_{2j2})
        u64 accD[4][4], accX[4][4];
#pragma unroll
        for (int i = 0; i < 4; i++)
#pragma unroll
            for (int j = 0; j < 4; j++) { accD[i][j] = 0ull; accX[i][j] = 0ull; }

        for (int kt = 0; kt < DIM; kt += 8) {
            float4 xv = *(const float4*)&X[(size_t)(row0 + lr) * DIM + kt + lk];
            float4 cv = *(const float4*)&g_cent[(size_t)(col0 + lr) * DIM + kt + lk];
            __syncthreads();
            Xs[lk + 0][lr] = xv.x; Xs[lk + 1][lr] = xv.y;
            Xs[lk + 2][lr] = xv.z; Xs[lk + 3][lr] = xv.w;
            Cs[lk + 0][lr] = cv.x; Cs[lk + 1][lr] = cv.y;
            Cs[lk + 2][lr] = cv.z; Cs[lk + 3][lr] = cv.w;
            __syncthreads();
#pragma unroll
            for (int kk = 0; kk < 8; kk++) {
                float4 a0 = *(float4*)&Xs[kk][ty * 8];
                float4 a1 = *(float4*)&Xs[kk][ty * 8 + 4];
                float4 b0 = *(float4*)&Cs[kk][tx * 8];
                float4 b1 = *(float4*)&Cs[kk][tx * 8 + 4];
                u64 a2[4] = { pack2(a0.x, a0.y), pack2(a0.z, a0.w),
                              pack2(a1.x, a1.y), pack2(a1.z, a1.w) };
                u64 b2[4] = { pack2(b0.x, b0.y), pack2(b0.z, b0.w),
                              pack2(b1.x, b1.y), pack2(b1.z, b1.w) };
                u64 b2s[4];
#pragma unroll
                for (int j = 0; j < 4; j++) b2s[j] = swap_halves(b2[j]);
#pragma unroll
                for (int i = 0; i < 4; i++)
#pragma unroll
                    for (int j = 0; j < 4; j++) {
                        accD[i][j] = fma2(a2[i], b2[j], accD[i][j]);
                        accX[i][j] = fma2(a2[i], b2s[j], accX[i][j]);
                    }
            }
        }
        // fused argmin epilogue; cols processed ascending per row -> first-min
#pragma unroll
        for (int j2 = 0; j2 < 4; j2++) {
            int c0 = col0 + tx * 8 + 2 * j2;
            float cs0 = g_csq[c0];
            float cs1 = g_csq[c0 + 1];
#pragma unroll
            for (int i2 = 0; i2 < 4; i2++) {
                float dlo, dhi, xlo, xhi;
                unpack2(accD[i2][j2], dlo, dhi);
                unpack2(accX[i2][j2], xlo, xhi);
                int ra = 2 * i2, rb = 2 * i2 + 1;
                float s;
                s = cs0 - 2.0f * dlo;                 // row ra, col c0
                if (s < best[ra]) { best[ra] = s; bidx[ra] = c0; }
                s = cs1 - 2.0f * xlo;                 // row ra, col c0+1
                if (s < best[ra]) { best[ra] = s; bidx[ra] = c0 + 1; }
                s = cs0 - 2.0f * xhi;                 // row rb, col c0
                if (s < best[rb]) { best[rb] = s; bidx[rb] = c0; }
                s = cs1 - 2.0f * dhi;                 // row rb, col c0+1
                if (s < best[rb]) { best[rb] = s; bidx[rb] = c0 + 1; }
            }
        }
        __syncthreads();
    }
#pragma unroll
    for (int i = 0; i < 8; i++) {
        rbest[ty * 8 + i][tx] = best[i];
        ridx[ty * 8 + i][tx] = bidx[i];
    }
    __syncthreads();
    if (tid < 128) {
        float bv = rbest[tid][0]; int bi = ridx[tid][0];
#pragma unroll
        for (int t = 1; t < 16; t++) {
            float v = rbest[tid][t]; int c = ridx[tid][t];
            if (v < bv || (v == bv && c < bi)) { bv = v; bi = c; }
        }
        g_idx[row0 + tid] = bi;
    }
}

__global__ void zero_sums(void) {
    int t = blockIdx.x * blockDim.x + threadIdx.x;
    if (t < N_CLU * DIM) g_sums[t] = 0.f;
    if (t < N_CLU) g_counts[t] = 0;
}

__global__ void scatter_add(const float* __restrict__ X) {
    int p = blockIdx.x;
    int c = g_idx[p];
    const float4* src = (const float4*)&X[(size_t)p * DIM];
    float4* dst = (float4*)&g_sums[(size_t)c * DIM];
    atomicAdd(&dst[threadIdx.x], src[threadIdx.x]);   // 256 x float4
    if (threadIdx.x == 0) atomicAdd(&g_counts[c], 1);
}

__global__ void finalize_cent(void) {
    int c = blockIdx.x;
    int cnt = g_counts[c];
    float fc = (float)cnt;
    for (int k = threadIdx.x; k < DIM; k += 256)
        g_cent[(size_t)c * DIM + k] = (cnt > 0) ? g_sums[(size_t)c * DIM + k] / fc : 0.f;
}

// ---------------- final per-batch compression ----------------
__global__ void zero_out(float* __restrict__ out) {
    int t = blockIdx.x * blockDim.x + threadIdx.x;
    out[t] = 0.f;
    if (t < NBATCH * N_CLU) g_counts2[t] = 0;
}

__global__ void scatter_out(const float* __restrict__ X, float* __restrict__ out) {
    int p = blockIdx.x;
    int b = p >> 11;                 // /2048
    int s = b * N_CLU + g_idx[p];
    const float4* src = (const float4*)&X[(size_t)p * DIM];
    float4* dst = (float4*)&out[(size_t)s * DIM];
    atomicAdd(&dst[threadIdx.x], src[threadIdx.x]);
    if (threadIdx.x == 0) atomicAdd(&g_counts2[s], 1);
}

__global__ void div_out(float* __restrict__ out) {
    int s = blockIdx.x;
    int cnt = g_counts2[s];
    if (cnt <= 0) return;            // stays zero (matches reference where())
    float fc = (float)cnt;
    for (int k = threadIdx.x; k < 256 * 4; k += 256) ;  // (no-op; kept minimal)
    for (int k = threadIdx.x; k < DIM; k += 256)
        out[(size_t)s * DIM + k] /= fc;
}

// ---------------- driver ----------------
static void run_full_sort() {
    sort_local<<<N_PTS / CHUNK, 512>>>();
    for (int k = 2 * CHUNK; k <= N_PTS; k <<= 1) {
        for (int j = k >> 1; j >= CHUNK; j >>= 1)
            sort_global<<<N_PTS / 2 / 256, 256>>>(k, j);
        sort_merge<<<N_PTS / CHUNK, 512>>>(k);
    }
}

extern "C" void kernel_launch(void* const* d_in, const int* in_sizes, int n_in,
                              void* d_out, int out_size) {
    (void)in_sizes; (void)n_in; (void)out_size;
    const float* X = (const float*)d_in[0];
    float* out = (float*)d_out;

    // jax.random.key(42) -> threefry key (0, 42)
    // partitionable split: keys_i = T(key, (0, i)); key,subkey = rows 0,1
    u32 K1a, K1b, S1a, S1b, S2a, S2b;
    tf2x32(0u, 42u, 0u, 0u, K1a, K1b);     // new key after round-1 split
    tf2x32(0u, 42u, 0u, 1u, S1a, S1b);     // round-1 subkey
    tf2x32(K1a, K1b, 0u, 1u, S2a, S2b);    // round-2 subkey

    // shuffle round 1: sort (bits1, i); values are arange -> low bits = value
    gen_keys_kernel<<<N_PTS / 256, 256>>>(S1a, S1b);
    run_full_sort();
    extract_val<<<N_PTS / 256, 256>>>();
    // shuffle round 2
    gen_keys_kernel<<<N_PTS / 256, 256>>>(S2a, S2b);
    run_full_sort();

    gather_init<<<N_CLU, 256>>>(X);

    for (int it = 0; it < 10; it++) {
        csq_kernel<<<N_CLU, 256>>>();
        assign_kernel<<<N_PTS / 128, 256>>>(X);
        zero_sums<<<(N_CLU * DIM) / 256, 256>>>();
        scatter_add<<<N_PTS, 256>>>(X);
        finalize_cent<<<N_CLU, 256>>>();
    }

    zero_out<<<(NBATCH * N_CLU * DIM) / 1024, 1024>>>(out);
    scatter_out<<<N_PTS, 256>>>(X, out);
    div_out<<<NBATCH * N_CLU, 256>>>(out);
}

// round 5
// speedup vs baseline: 1.7046x; 1.6900x over previous
#include <cuda_runtime.h>
#include <cuda_bf16.h>

typedef unsigned int u32;
typedef unsigned long long u64;

#define N_PTS 32768
#define N_CLU 512
#define DIM   1024
#define NBATCH 16
#define CHUNK 4096
#define EPS   0.05f

// ---------------- scratch (device globals; no allocation) ----------------
__device__ u64 g_sortbuf[N_PTS];
__device__ int g_val[N_PTS];
__device__ __align__(16) float g_cent[N_CLU * DIM];
__device__ float g_csq[N_CLU];
__device__ int g_idx[N_PTS];
__device__ __align__(16) float g_sums[N_CLU * DIM];
__device__ int g_counts[N_CLU];
__device__ int g_counts2[NBATCH * N_CLU];
__device__ __align__(16) float g_dist[N_PTS * N_CLU];   // approx distances

// bf16 split components (X: once per launch, C: per iteration)
__device__ __align__(128) __nv_bfloat16 g_xb0[N_PTS * DIM];
__device__ __align__(128) __nv_bfloat16 g_xb1[N_PTS * DIM];
__device__ __align__(128) __nv_bfloat16 g_cb0[N_CLU * DIM];
__device__ __align__(128) __nv_bfloat16 g_cb1[N_CLU * DIM];

__device__ __forceinline__ u32 smem_u32(const void* p) {
    u32 a;
    asm("{ .reg .u64 t; cvta.to.shared.u64 t, %1; cvt.u32.u64 %0, t; }"
        : "=r"(a) : "l"(p));
    return a;
}

#define LDSM4(r, addr) \
    asm volatile("ldmatrix.sync.aligned.m8n8.x4.shared.b16 {%0,%1,%2,%3}, [%4];" \
        : "=r"((r)[0]), "=r"((r)[1]), "=r"((r)[2]), "=r"((r)[3]) : "r"(addr))

#define MMA16816(d, a, b0_, b1_) \
    asm volatile("mma.sync.aligned.m16n8k16.row.col.f32.bf16.bf16.f32 " \
        "{%0,%1,%2,%3}, {%4,%5,%6,%7}, {%8,%9}, {%0,%1,%2,%3};" \
        : "+f"((d)[0]), "+f"((d)[1]), "+f"((d)[2]), "+f"((d)[3]) \
        : "r"((a)[0]), "r"((a)[1]), "r"((a)[2]), "r"((a)[3]), "r"(b0_), "r"(b1_))

// ---------------- Threefry-2x32 (matches jax._src.prng) ----------------
__host__ __device__ inline void tf2x32(u32 k0, u32 k1, u32 x0, u32 x1,
                                       u32& o0, u32& o1) {
    u32 ks2 = k0 ^ k1 ^ 0x1BD11BDAu;
    x0 += k0; x1 += k1;
#define TF_R(r) { x0 += x1; x1 = (x1 << (r)) | (x1 >> (32 - (r))); x1 ^= x0; }
    TF_R(13) TF_R(15) TF_R(26) TF_R(6)
    x0 += k1;  x1 += ks2 + 1u;
    TF_R(17) TF_R(29) TF_R(16) TF_R(24)
    x0 += ks2; x1 += k0 + 2u;
    TF_R(13) TF_R(15) TF_R(26) TF_R(6)
    x0 += k0;  x1 += k1 + 3u;
    TF_R(17) TF_R(29) TF_R(16) TF_R(24)
    x0 += k1;  x1 += ks2 + 4u;
    TF_R(13) TF_R(15) TF_R(26) TF_R(6)
    x0 += ks2; x1 += k0 + 5u;
#undef TF_R
    o0 = x0; o1 = x1;
}

__global__ void gen_keys_kernel(u32 sk0, u32 sk1) {
    int i = blockIdx.x * blockDim.x + threadIdx.x;
    if (i >= N_PTS) return;
    u32 a, b;
    tf2x32(sk0, sk1, 0u, (u32)i, a, b);
    g_sortbuf[i] = ((u64)(a ^ b) << 32) | (u32)i;
}

// ---------------- bitonic sort (stable via (key,pos) composite) ----------------
__global__ void sort_local(void) {
    __shared__ u64 s[CHUNK];
    int base = blockIdx.x * CHUNK;
    for (int t = threadIdx.x; t < CHUNK; t += blockDim.x) s[t] = g_sortbuf[base + t];
    __syncthreads();
    for (int k = 2; k <= CHUNK; k <<= 1) {
        for (int j = k >> 1; j > 0; j >>= 1) {
            for (int t = threadIdx.x; t < CHUNK / 2; t += blockDim.x) {
                int i = ((t & ~(j - 1)) << 1) | (t & (j - 1));
                int l = i | j;
                bool asc = (((base + i) & k) == 0);
                u64 x = s[i], y = s[l];
                if ((x > y) == asc) { s[i] = y; s[l] = x; }
            }
            __syncthreads();
        }
    }
    for (int t = threadIdx.x; t < CHUNK; t += blockDim.x) g_sortbuf[base + t] = s[t];
}

__global__ void sort_global(int k, int j) {
    int t = blockIdx.x * blockDim.x + threadIdx.x;
    int i = ((t & ~(j - 1)) << 1) | (t & (j - 1));
    int l = i | j;
    bool asc = ((i & k) == 0);
    u64 x = g_sortbuf[i], y = g_sortbuf[l];
    if ((x > y) == asc) { g_sortbuf[i] = y; g_sortbuf[l] = x; }
}

__global__ void sort_merge(int k) {
    __shared__ u64 s[CHUNK];
    int base = blockIdx.x * CHUNK;
    bool asc = ((base & k) == 0);
    for (int t = threadIdx.x; t < CHUNK; t += blockDim.x) s[t] = g_sortbuf[base + t];
    __syncthreads();
    for (int j = CHUNK / 2; j > 0; j >>= 1) {
        for (int t = threadIdx.x; t < CHUNK / 2; t += blockDim.x) {
            int i = ((t & ~(j - 1)) << 1) | (t & (j - 1));
            int l = i | j;
            u64 x = s[i], y = s[l];
            if ((x > y) == asc) { s[i] = y; s[l] = x; }
        }
        __syncthreads();
    }
    for (int t = threadIdx.x; t < CHUNK; t += blockDim.x) g_sortbuf[base + t] = s[t];
}

__global__ void extract_val(void) {
    int i = blockIdx.x * blockDim.x + threadIdx.x;
    if (i < N_PTS) g_val[i] = (int)(g_sortbuf[i] & 0xFFFFFFFFu);
}

__global__ void gather_init(const float* __restrict__ X) {
    int c = blockIdx.x;
    int pos = (int)(g_sortbuf[c] & 0xFFFFFFFFu);
    int src = g_val[pos];
    const float4* s = (const float4*)&X[(size_t)src * DIM];
    float4* d = (float4*)&g_cent[(size_t)c * DIM];
    d[threadIdx.x] = s[threadIdx.x];
}

// ---------------- bf16 splits (2-way) ----------------
__global__ void convert_x(const float* __restrict__ X) {
    int i = blockIdx.x * blockDim.x + threadIdx.x;
    float v = X[i];
    __nv_bfloat16 b0 = __float2bfloat16_rn(v);
    float r = v - __bfloat162float(b0);
    g_xb0[i] = b0;
    g_xb1[i] = __float2bfloat16_rn(r);
}

__global__ void convert_c(void) {
    int i = blockIdx.x * blockDim.x + threadIdx.x;
    float v = g_cent[i];
    __nv_bfloat16 b0 = __float2bfloat16_rn(v);
    float r = v - __bfloat162float(b0);
    g_cb0[i] = b0;
    g_cb1[i] = __float2bfloat16_rn(r);
}

__global__ void csq_kernel(void) {
    int c = blockIdx.x;
    const float* row = &g_cent[(size_t)c * DIM];
    float s = 0.f;
    for (int t = threadIdx.x; t < DIM; t += 256) { float v = row[t]; s += v * v; }
    __shared__ float red[256];
    red[threadIdx.x] = s; __syncthreads();
    for (int o = 128; o > 0; o >>= 1) {
        if (threadIdx.x < o) red[threadIdx.x] += red[threadIdx.x + o];
        __syncthreads();
    }
    if (threadIdx.x == 0) g_csq[c] = red[0];
}

// ---------------- Phase 1: HMMA approx distance matrix ----------------
// CTA: 128 points x 512 clusters (4 col passes of 128). 8 warps.
// 3 bf16 component GEMMs (b0c0 + b0c1 + b1c0) = K of 3*1024, chunks of 32.
#define SSTR 40
#define NCH 96

__global__ void __launch_bounds__(256) dist_hmma(void) {
    __shared__ __nv_bfloat16 sA[2][128 * SSTR];
    __shared__ __nv_bfloat16 sB[2][128 * SSTR];
    __shared__ float s_csq[N_CLU];

    int tid = threadIdx.x, wid = tid >> 5, lid = tid & 31;
    int row0 = blockIdx.x * 128;
    for (int j = tid; j < N_CLU; j += 256) s_csq[j] = g_csq[j];

    int ar0 = tid >> 2,          as0 = (tid & 3);
    int ar1 = (tid + 256) >> 2,  as1 = ((tid + 256) & 3);

    u32 sAb = smem_u32(sA), sBb = smem_u32(sB);
    int l16 = lid & 15, lh = lid >> 4;
    u32 aoff = (u32)(((wid * 16 + l16) * SSTR + lh * 8) * 2);
    int bm = lid >> 3, bl = lid & 7;
    u32 boff = (u32)(((((bm >> 1) * 8) + bl) * SSTR + (bm & 1) * 8) * 2);

    int erow = lid >> 2;
    int ecol = (lid & 3) * 2;

    for (int nt = 0; nt < 4; nt++) {
        int col0 = nt * 128;
        float acc[16][4];
#pragma unroll
        for (int t = 0; t < 16; t++)
#pragma unroll
            for (int i = 0; i < 4; i++) acc[t][i] = 0.f;

        uint4 ra0, ra1, rb0, rb1;
        {   // prologue: chunk 0 = (x0, c0), kt 0
            ra0 = *(const uint4*)(g_xb0 + (size_t)(row0 + ar0) * DIM + as0 * 8);
            ra1 = *(const uint4*)(g_xb0 + (size_t)(row0 + ar1) * DIM + as1 * 8);
            rb0 = *(const uint4*)(g_cb0 + (size_t)(col0 + ar0) * DIM + as0 * 8);
            rb1 = *(const uint4*)(g_cb0 + (size_t)(col0 + ar1) * DIM + as1 * 8);
        }
        *(uint4*)&sA[0][ar0 * SSTR + as0 * 8] = ra0;
        *(uint4*)&sA[0][ar1 * SSTR + as1 * 8] = ra1;
        *(uint4*)&sB[0][ar0 * SSTR + as0 * 8] = rb0;
        *(uint4*)&sB[0][ar1 * SSTR + as1 * 8] = rb1;
        __syncthreads();

        for (int c = 0; c < NCH; c++) {
            int buf = c & 1;
            bool more = (c + 1 < NCH);
            if (more) {
                int nc = c + 1;
                int comp = nc >> 5, kk = (nc & 31) << 5;
                const __nv_bfloat16* ap = (comp == 2) ? g_xb1 : g_xb0;
                const __nv_bfloat16* bp = (comp == 1) ? g_cb1 : g_cb0;
                ra0 = *(const uint4*)(ap + (size_t)(row0 + ar0) * DIM + kk + as0 * 8);
                ra1 = *(const uint4*)(ap + (size_t)(row0 + ar1) * DIM + kk + as1 * 8);
                rb0 = *(const uint4*)(bp + (size_t)(col0 + ar0) * DIM + kk + as0 * 8);
                rb1 = *(const uint4*)(bp + (size_t)(col0 + ar1) * DIM + kk + as1 * 8);
            }
            u32 abase = sAb + buf * (128 * SSTR * 2);
            u32 bbase = sBb + buf * (128 * SSTR * 2);
            u32 afr0[4], afr1[4];
            LDSM4(afr0, abase + aoff);
            LDSM4(afr1, abase + aoff + 32);
#pragma unroll
            for (int p = 0; p < 8; p++) {
                u32 bb = bbase + boff + (u32)(p * 16 * SSTR * 2);
                u32 bf[4];
                LDSM4(bf, bb);
                MMA16816(acc[2 * p],     afr0, bf[0], bf[1]);
                MMA16816(acc[2 * p + 1], afr0, bf[2], bf[3]);
                LDSM4(bf, bb + 32);
                MMA16816(acc[2 * p],     afr1, bf[0], bf[1]);
                MMA16816(acc[2 * p + 1], afr1, bf[2], bf[3]);
            }
            if (more) {
                __syncthreads();
                int nb = buf ^ 1;
                *(uint4*)&sA[nb][ar0 * SSTR + as0 * 8] = ra0;
                *(uint4*)&sA[nb][ar1 * SSTR + as1 * 8] = ra1;
                *(uint4*)&sB[nb][ar0 * SSTR + as0 * 8] = rb0;
                *(uint4*)&sB[nb][ar1 * SSTR + as1 * 8] = rb1;
                __syncthreads();
            }
        }
        // store approx distances csq - 2*dot
        {
            int r = row0 + wid * 16 + erow;
#pragma unroll
            for (int t = 0; t < 16; t++) {
                int cbase = col0 + t * 8 + ecol;
                float cs0 = s_csq[cbase], cs1 = s_csq[cbase + 1];
                float2 v0 = make_float2(cs0 - 2.0f * acc[t][0], cs1 - 2.0f * acc[t][1]);
                float2 v1 = make_float2(cs0 - 2.0f * acc[t][2], cs1 - 2.0f * acc[t][3]);
                *(float2*)&g_dist[(size_t)r * N_CLU + cbase] = v0;
                *(float2*)&g_dist[(size_t)(r + 8) * N_CLU + cbase] = v1;
            }
        }
        __syncthreads();
    }
}

// ---------------- Phase 2: exact fp32 rescue ----------------
// One warp per point. Candidates = approx dist within EPS of approx min.
// Exact fp32 dot for each candidate; argmin with ascending tie-break.
__global__ void __launch_bounds__(256) refine_assign(const float* __restrict__ X) {
    int wip = (blockIdx.x * blockDim.x + threadIdx.x) >> 5;
    int lane = threadIdx.x & 31;
    const float* drow = &g_dist[(size_t)wip * N_CLU];
    float d[16];
    float m = 3.4e38f;
#pragma unroll
    for (int k = 0; k < 16; k++) { d[k] = drow[k * 32 + lane]; m = fminf(m, d[k]); }
#pragma unroll
    for (int o = 16; o; o >>= 1) m = fminf(m, __shfl_xor_sync(0xFFFFFFFFu, m, o));
    float thr = m + EPS;
    float best = 3.4e38f;
    int bidx = N_CLU;
    const float* xrow = &X[(size_t)wip * DIM];
#pragma unroll 1
    for (int k = 0; k < 16; k++) {
        u32 mask = __ballot_sync(0xFFFFFFFFu, d[k] < thr);
        while (mask) {
            int src = __ffs(mask) - 1;
            mask &= mask - 1;
            int c = k * 32 + src;
            const float* crow = &g_cent[(size_t)c * DIM];
            float s = 0.f;
#pragma unroll 8
            for (int j = lane; j < DIM; j += 32) s += xrow[j] * crow[j];
#pragma unroll
            for (int o = 16; o; o >>= 1) s += __shfl_xor_sync(0xFFFFFFFFu, s, o);
            float dist = g_csq[c] - 2.0f * s;
            if (dist < best || (dist == best && c < bidx)) { best = dist; bidx = c; }
        }
    }
    if (lane == 0) g_idx[wip] = bidx;
}

// ---------------- centroid update / output ----------------
__global__ void zero_sums(void) {
    int t = blockIdx.x * blockDim.x + threadIdx.x;
    if (t < N_CLU * DIM) g_sums[t] = 0.f;
    if (t < N_CLU) g_counts[t] = 0;
}

__global__ void scatter_add(const float* __restrict__ X) {
    int p = blockIdx.x;
    int c = g_idx[p];
    const float4* src = (const float4*)&X[(size_t)p * DIM];
    float4* dst = (float4*)&g_sums[(size_t)c * DIM];
    atomicAdd(&dst[threadIdx.x], src[threadIdx.x]);
    if (threadIdx.x == 0) atomicAdd(&g_counts[c], 1);
}

__global__ void finalize_cent(void) {
    int c = blockIdx.x;
    int cnt = g_counts[c];
    float fc = (float)cnt;
    for (int k = threadIdx.x; k < DIM; k += 256)
        g_cent[(size_t)c * DIM + k] = (cnt > 0) ? g_sums[(size_t)c * DIM + k] / fc : 0.f;
}

__global__ void zero_out(float* __restrict__ out) {
    int t = blockIdx.x * blockDim.x + threadIdx.x;
    out[t] = 0.f;
    if (t < NBATCH * N_CLU) g_counts2[t] = 0;
}

__global__ void scatter_out(const float* __restrict__ X, float* __restrict__ out) {
    int p = blockIdx.x;
    int b = p >> 11;
    int s = b * N_CLU + g_idx[p];
    const float4* src = (const float4*)&X[(size_t)p * DIM];
    float4* dst = (float4*)&out[(size_t)s * DIM];
    atomicAdd(&dst[threadIdx.x], src[threadIdx.x]);
    if (threadIdx.x == 0) atomicAdd(&g_counts2[s], 1);
}

__global__ void div_out(float* __restrict__ out) {
    int s = blockIdx.x;
    int cnt = g_counts2[s];
    if (cnt <= 0) return;
    float fc = (float)cnt;
    for (int k = threadIdx.x; k < DIM; k += 256)
        out[(size_t)s * DIM + k] /= fc;
}

// ---------------- driver ----------------
static void run_full_sort() {
    sort_local<<<N_PTS / CHUNK, 512>>>();
    for (int k = 2 * CHUNK; k <= N_PTS; k <<= 1) {
        for (int j = k >> 1; j >= CHUNK; j >>= 1)
            sort_global<<<N_PTS / 2 / 256, 256>>>(k, j);
        sort_merge<<<N_PTS / CHUNK, 512>>>(k);
    }
}

extern "C" void kernel_launch(void* const* d_in, const int* in_sizes, int n_in,
                              void* d_out, int out_size) {
    (void)in_sizes; (void)n_in; (void)out_size;
    const float* X = (const float*)d_in[0];
    float* out = (float*)d_out;

    // jax.random.key(42): partitionable threefry shuffle, 2 rounds
    u32 K1a, K1b, S1a, S1b, S2a, S2b;
    tf2x32(0u, 42u, 0u, 0u, K1a, K1b);
    tf2x32(0u, 42u, 0u, 1u, S1a, S1b);
    tf2x32(K1a, K1b, 0u, 1u, S2a, S2b);

    gen_keys_kernel<<<N_PTS / 256, 256>>>(S1a, S1b);
    run_full_sort();
    extract_val<<<N_PTS / 256, 256>>>();
    gen_keys_kernel<<<N_PTS / 256, 256>>>(S2a, S2b);
    run_full_sort();

    gather_init<<<N_CLU, 256>>>(X);
    convert_x<<<N_PTS, 1024>>>(X);

    for (int it = 0; it < 10; it++) {
        convert_c<<<N_CLU, 1024>>>();
        csq_kernel<<<N_CLU, 256>>>();
        dist_hmma<<<N_PTS / 128, 256>>>();
        refine_assign<<<N_PTS * 32 / 256, 256>>>(X);
        zero_sums<<<(N_CLU * DIM) / 256, 256>>>();
        scatter_add<<<N_PTS, 256>>>(X);
        finalize_cent<<<N_CLU, 256>>>();
    }

    zero_out<<<(NBATCH * N_CLU * DIM) / 1024, 1024>>>(out);
    scatter_out<<<N_PTS, 256>>>(X, out);
    div_out<<<NBATCH * N_CLU, 256>>>(out);
}

// round 7
// speedup vs baseline: 2.9129x; 1.7089x over previous
#include <cuda_runtime.h>
#include <cuda_bf16.h>

typedef unsigned int u32;
typedef unsigned long long u64;

#define N_PTS 32768
#define N_CLU 512
#define DIM   1024
#define NBATCH 16
#define CHUNK 4096
#define EPS   8.0f

// ---------------- scratch (device globals; no allocation) ----------------
__device__ u64 g_sortbuf[N_PTS];
__device__ int g_val[N_PTS];
__device__ __align__(16) float g_cent[N_CLU * DIM];
__device__ float g_csq[N_CLU];
__device__ int g_idx[N_PTS];
__device__ __align__(16) float g_sums[N_CLU * DIM];
__device__ int g_counts[N_CLU];
__device__ int g_counts2[NBATCH * N_CLU];
__device__ __align__(16) float g_dist[N_PTS * N_CLU];   // approx distances

// bf16 copies (X: once per launch, C: per iteration)
__device__ __align__(128) __nv_bfloat16 g_xb0[N_PTS * DIM];
__device__ __align__(128) __nv_bfloat16 g_cb0[N_CLU * DIM];

__device__ __forceinline__ u32 smem_u32(const void* p) {
    u32 a;
    asm("{ .reg .u64 t; cvta.to.shared.u64 t, %1; cvt.u32.u64 %0, t; }"
        : "=r"(a) : "l"(p));
    return a;
}

#define LDSM4(r, addr) \
    asm volatile("ldmatrix.sync.aligned.m8n8.x4.shared.b16 {%0,%1,%2,%3}, [%4];" \
        : "=r"((r)[0]), "=r"((r)[1]), "=r"((r)[2]), "=r"((r)[3]) : "r"(addr))

#define MMA16816(d, a, b0_, b1_) \
    asm volatile("mma.sync.aligned.m16n8k16.row.col.f32.bf16.bf16.f32 " \
        "{%0,%1,%2,%3}, {%4,%5,%6,%7}, {%8,%9}, {%0,%1,%2,%3};" \
        : "+f"((d)[0]), "+f"((d)[1]), "+f"((d)[2]), "+f"((d)[3]) \
        : "r"((a)[0]), "r"((a)[1]), "r"((a)[2]), "r"((a)[3]), "r"(b0_), "r"(b1_))

// ---------------- Threefry-2x32 (matches jax._src.prng) ----------------
__host__ __device__ inline void tf2x32(u32 k0, u32 k1, u32 x0, u32 x1,
                                       u32& o0, u32& o1) {
    u32 ks2 = k0 ^ k1 ^ 0x1BD11BDAu;
    x0 += k0; x1 += k1;
#define TF_R(r) { x0 += x1; x1 = (x1 << (r)) | (x1 >> (32 - (r))); x1 ^= x0; }
    TF_R(13) TF_R(15) TF_R(26) TF_R(6)
    x0 += k1;  x1 += ks2 + 1u;
    TF_R(17) TF_R(29) TF_R(16) TF_R(24)
    x0 += ks2; x1 += k0 + 2u;
    TF_R(13) TF_R(15) TF_R(26) TF_R(6)
    x0 += k0;  x1 += k1 + 3u;
    TF_R(17) TF_R(29) TF_R(16) TF_R(24)
    x0 += k1;  x1 += ks2 + 4u;
    TF_R(13) TF_R(15) TF_R(26) TF_R(6)
    x0 += ks2; x1 += k0 + 5u;
#undef TF_R
    o0 = x0; o1 = x1;
}

__global__ void gen_keys_kernel(u32 sk0, u32 sk1) {
    int i = blockIdx.x * blockDim.x + threadIdx.x;
    if (i >= N_PTS) return;
    u32 a, b;
    tf2x32(sk0, sk1, 0u, (u32)i, a, b);
    g_sortbuf[i] = ((u64)(a ^ b) << 32) | (u32)i;
}

// ---------------- bitonic sort (stable via (key,pos) composite) ----------------
__global__ void sort_local(void) {
    __shared__ u64 s[CHUNK];
    int base = blockIdx.x * CHUNK;
    for (int t = threadIdx.x; t < CHUNK; t += blockDim.x) s[t] = g_sortbuf[base + t];
    __syncthreads();
    for (int k = 2; k <= CHUNK; k <<= 1) {
        for (int j = k >> 1; j > 0; j >>= 1) {
            for (int t = threadIdx.x; t < CHUNK / 2; t += blockDim.x) {
                int i = ((t & ~(j - 1)) << 1) | (t & (j - 1));
                int l = i | j;
                bool asc = (((base + i) & k) == 0);
                u64 x = s[i], y = s[l];
                if ((x > y) == asc) { s[i] = y; s[l] = x; }
            }
            __syncthreads();
        }
    }
    for (int t = threadIdx.x; t < CHUNK; t += blockDim.x) g_sortbuf[base + t] = s[t];
}

__global__ void sort_global(int k, int j) {
    int t = blockIdx.x * blockDim.x + threadIdx.x;
    int i = ((t & ~(j - 1)) << 1) | (t & (j - 1));
    int l = i | j;
    bool asc = ((i & k) == 0);
    u64 x = g_sortbuf[i], y = g_sortbuf[l];
    if ((x > y) == asc) { g_sortbuf[i] = y; g_sortbuf[l] = x; }
}

__global__ void sort_merge(int k) {
    __shared__ u64 s[CHUNK];
    int base = blockIdx.x * CHUNK;
    bool asc = ((base & k) == 0);
    for (int t = threadIdx.x; t < CHUNK; t += blockDim.x) s[t] = g_sortbuf[base + t];
    __syncthreads();
    for (int j = CHUNK / 2; j > 0; j >>= 1) {
        for (int t = threadIdx.x; t < CHUNK / 2; t += blockDim.x) {
            int i = ((t & ~(j - 1)) << 1) | (t & (j - 1));
            int l = i | j;
            u64 x = s[i], y = s[l];
            if ((x > y) == asc) { s[i] = y; s[l] = x; }
        }
        __syncthreads();
    }
    for (int t = threadIdx.x; t < CHUNK; t += blockDim.x) g_sortbuf[base + t] = s[t];
}

__global__ void extract_val(void) {
    int i = blockIdx.x * blockDim.x + threadIdx.x;
    if (i < N_PTS) g_val[i] = (int)(g_sortbuf[i] & 0xFFFFFFFFu);
}

__global__ void gather_init(const float* __restrict__ X) {
    int c = blockIdx.x;
    int pos = (int)(g_sortbuf[c] & 0xFFFFFFFFu);
    int src = g_val[pos];
    const float4* s = (const float4*)&X[(size_t)src * DIM];
    float4* d = (float4*)&g_cent[(size_t)c * DIM];
    d[threadIdx.x] = s[threadIdx.x];
}

// ---------------- bf16 conversion (plain round-to-nearest) ----------------
__global__ void convert_x(const float* __restrict__ X) {
    int i = blockIdx.x * blockDim.x + threadIdx.x;
    g_xb0[i] = __float2bfloat16_rn(X[i]);
}

__global__ void convert_c(void) {
    int i = blockIdx.x * blockDim.x + threadIdx.x;
    g_cb0[i] = __float2bfloat16_rn(g_cent[i]);
}

__global__ void csq_kernel(void) {
    int c = blockIdx.x;
    const float* row = &g_cent[(size_t)c * DIM];
    float s = 0.f;
    for (int t = threadIdx.x; t < DIM; t += 256) { float v = row[t]; s += v * v; }
    __shared__ float red[256];
    red[threadIdx.x] = s; __syncthreads();
    for (int o = 128; o > 0; o >>= 1) {
        if (threadIdx.x < o) red[threadIdx.x] += red[threadIdx.x + o];
        __syncthreads();
    }
    if (threadIdx.x == 0) g_csq[c] = red[0];
}

// ---------------- Phase 1: single bf16 HMMA approx distance matrix ----------------
// CTA: 128 points x 512 clusters (4 col passes of 128). 8 warps.
// K = 1024, chunks of 32, double-buffered smem (stride 40 bf16, conflict-free).
#define SSTR 40
#define NCH 32

__global__ void __launch_bounds__(256) dist_hmma(void) {
    __shared__ __nv_bfloat16 sA[2][128 * SSTR];
    __shared__ __nv_bfloat16 sB[2][128 * SSTR];
    __shared__ float s_csq[N_CLU];

    int tid = threadIdx.x, wid = tid >> 5, lid = tid & 31;
    int row0 = blockIdx.x * 128;
    for (int j = tid; j < N_CLU; j += 256) s_csq[j] = g_csq[j];

    int ar0 = tid >> 2,          as0 = (tid & 3);
    int ar1 = (tid + 256) >> 2,  as1 = ((tid + 256) & 3);

    u32 sAb = smem_u32(sA), sBb = smem_u32(sB);
    int l16 = lid & 15, lh = lid >> 4;
    u32 aoff = (u32)(((wid * 16 + l16) * SSTR + lh * 8) * 2);
    int bm = lid >> 3, bl = lid & 7;
    u32 boff = (u32)(((((bm >> 1) * 8) + bl) * SSTR + (bm & 1) * 8) * 2);

    int erow = lid >> 2;
    int ecol = (lid & 3) * 2;

    for (int nt = 0; nt < 4; nt++) {
        int col0 = nt * 128;
        float acc[16][4];
#pragma unroll
        for (int t = 0; t < 16; t++)
#pragma unroll
            for (int i = 0; i < 4; i++) acc[t][i] = 0.f;

        uint4 ra0, ra1, rb0, rb1;
        {   // prologue: chunk 0
            ra0 = *(const uint4*)(g_xb0 + (size_t)(row0 + ar0) * DIM + as0 * 8);
            ra1 = *(const uint4*)(g_xb0 + (size_t)(row0 + ar1) * DIM + as1 * 8);
            rb0 = *(const uint4*)(g_cb0 + (size_t)(col0 + ar0) * DIM + as0 * 8);
            rb1 = *(const uint4*)(g_cb0 + (size_t)(col0 + ar1) * DIM + as1 * 8);
        }
        *(uint4*)&sA[0][ar0 * SSTR + as0 * 8] = ra0;
        *(uint4*)&sA[0][ar1 * SSTR + as1 * 8] = ra1;
        *(uint4*)&sB[0][ar0 * SSTR + as0 * 8] = rb0;
        *(uint4*)&sB[0][ar1 * SSTR + as1 * 8] = rb1;
        __syncthreads();

        for (int c = 0; c < NCH; c++) {
            int buf = c & 1;
            bool more = (c + 1 < NCH);
            if (more) {
                int kk = (c + 1) << 5;
                ra0 = *(const uint4*)(g_xb0 + (size_t)(row0 + ar0) * DIM + kk + as0 * 8);
                ra1 = *(const uint4*)(g_xb0 + (size_t)(row0 + ar1) * DIM + kk + as1 * 8);
                rb0 = *(const uint4*)(g_cb0 + (size_t)(col0 + ar0) * DIM + kk + as0 * 8);
                rb1 = *(const uint4*)(g_cb0 + (size_t)(col0 + ar1) * DIM + kk + as1 * 8);
            }
            u32 abase = sAb + buf * (128 * SSTR * 2);
            u32 bbase = sBb + buf * (128 * SSTR * 2);
            u32 afr0[4], afr1[4];
            LDSM4(afr0, abase + aoff);
            LDSM4(afr1, abase + aoff + 32);
#pragma unroll
            for (int p = 0; p < 8; p++) {
                u32 bb = bbase + boff + (u32)(p * 16 * SSTR * 2);
                u32 bf[4];
                LDSM4(bf, bb);
                MMA16816(acc[2 * p],     afr0, bf[0], bf[1]);
                MMA16816(acc[2 * p + 1], afr0, bf[2], bf[3]);
                LDSM4(bf, bb + 32);
                MMA16816(acc[2 * p],     afr1, bf[0], bf[1]);
                MMA16816(acc[2 * p + 1], afr1, bf[2], bf[3]);
            }
            if (more) {
                __syncthreads();
                int nb = buf ^ 1;
                *(uint4*)&sA[nb][ar0 * SSTR + as0 * 8] = ra0;
                *(uint4*)&sA[nb][ar1 * SSTR + as1 * 8] = ra1;
                *(uint4*)&sB[nb][ar0 * SSTR + as0 * 8] = rb0;
                *(uint4*)&sB[nb][ar1 * SSTR + as1 * 8] = rb1;
                __syncthreads();
            }
        }
        // store approx distances csq - 2*dot
        {
            int r = row0 + wid * 16 + erow;
#pragma unroll
            for (int t = 0; t < 16; t++) {
                int cbase = col0 + t * 8 + ecol;
                float cs0 = s_csq[cbase], cs1 = s_csq[cbase + 1];
                float2 v0 = make_float2(cs0 - 2.0f * acc[t][0], cs1 - 2.0f * acc[t][1]);
                float2 v1 = make_float2(cs0 - 2.0f * acc[t][2], cs1 - 2.0f * acc[t][3]);
                *(float2*)&g_dist[(size_t)r * N_CLU + cbase] = v0;
                *(float2*)&g_dist[(size_t)(r + 8) * N_CLU + cbase] = v1;
            }
        }
        __syncthreads();
    }
}

// ---------------- Phase 2: exact fp32 rescue ----------------
// One warp per point. Candidates = approx dist within EPS of approx min.
// Exact fp32 dot for each candidate; argmin with ascending tie-break.
__global__ void __launch_bounds__(256) refine_assign(const float* __restrict__ X) {
    int wip = (blockIdx.x * blockDim.x + threadIdx.x) >> 5;
    int lane = threadIdx.x & 31;
    const float* drow = &g_dist[(size_t)wip * N_CLU];
    float d[16];
    float m = 3.4e38f;
#pragma unroll
    for (int k = 0; k < 16; k++) { d[k] = drow[k * 32 + lane]; m = fminf(m, d[k]); }
#pragma unroll
    for (int o = 16; o; o >>= 1) m = fminf(m, __shfl_xor_sync(0xFFFFFFFFu, m, o));
    float thr = m + EPS;
    float best = 3.4e38f;
    int bidx = N_CLU;
    const float* xrow = &X[(size_t)wip * DIM];
#pragma unroll 1
    for (int k = 0; k < 16; k++) {
        u32 mask = __ballot_sync(0xFFFFFFFFu, d[k] < thr);
        while (mask) {
            int src = __ffs(mask) - 1;
            mask &= mask - 1;
            int c = k * 32 + src;
            const float* crow = &g_cent[(size_t)c * DIM];
            float s = 0.f;
#pragma unroll 8
            for (int j = lane; j < DIM; j += 32) s += xrow[j] * crow[j];
#pragma unroll
            for (int o = 16; o; o >>= 1) s += __shfl_xor_sync(0xFFFFFFFFu, s, o);
            float dist = g_csq[c] - 2.0f * s;
            if (dist < best || (dist == best && c < bidx)) { best = dist; bidx = c; }
        }
    }
    if (lane == 0) g_idx[wip] = bidx;
}

// ---------------- centroid update / output ----------------
__global__ void zero_sums(void) {
    int t = blockIdx.x * blockDim.x + threadIdx.x;
    if (t < N_CLU * DIM) g_sums[t] = 0.f;
    if (t < N_CLU) g_counts[t] = 0;
}

__global__ void scatter_add(const float* __restrict__ X) {
    int p = blockIdx.x;
    int c = g_idx[p];
    const float4* src = (const float4*)&X[(size_t)p * DIM];
    float4* dst = (float4*)&g_sums[(size_t)c * DIM];
    atomicAdd(&dst[threadIdx.x], src[threadIdx.x]);
    if (threadIdx.x == 0) atomicAdd(&g_counts[c], 1);
}

__global__ void finalize_cent(void) {
    int c = blockIdx.x;
    int cnt = g_counts[c];
    float fc = (float)cnt;
    for (int k = threadIdx.x; k < DIM; k += 256)
        g_cent[(size_t)c * DIM + k] = (cnt > 0) ? g_sums[(size_t)c * DIM + k] / fc : 0.f;
}

__global__ void zero_out(float* __restrict__ out) {
    int t = blockIdx.x * blockDim.x + threadIdx.x;
    out[t] = 0.f;
    if (t < NBATCH * N_CLU) g_counts2[t] = 0;
}

__global__ void scatter_out(const float* __restrict__ X, float* __restrict__ out) {
    int p = blockIdx.x;
    int b = p >> 11;
    int s = b * N_CLU + g_idx[p];
    const float4* src = (const float4*)&X[(size_t)p * DIM];
    float4* dst = (float4*)&out[(size_t)s * DIM];
    atomicAdd(&dst[threadIdx.x], src[threadIdx.x]);
    if (threadIdx.x == 0) atomicAdd(&g_counts2[s], 1);
}

__global__ void div_out(float* __restrict__ out) {
    int s = blockIdx.x;
    int cnt = g_counts2[s];
    if (cnt <= 0) return;
    float fc = (float)cnt;
    for (int k = threadIdx.x; k < DIM; k += 256)
        out[(size_t)s * DIM + k] /= fc;
}

// ---------------- driver ----------------
static void run_full_sort() {
    sort_local<<<N_PTS / CHUNK, 512>>>();
    for (int k = 2 * CHUNK; k <= N_PTS; k <<= 1) {
        for (int j = k >> 1; j >= CHUNK; j >>= 1)
            sort_global<<<N_PTS / 2 / 256, 256>>>(k, j);
        sort_merge<<<N_PTS / CHUNK, 512>>>(k);
    }
}

extern "C" void kernel_launch(void* const* d_in, const int* in_sizes, int n_in,
                              void* d_out, int out_size) {
    (void)in_sizes; (void)n_in; (void)out_size;
    const float* X = (const float*)d_in[0];
    float* out = (float*)d_out;

    // jax.random.key(42): partitionable threefry shuffle, 2 rounds
    u32 K1a, K1b, S1a, S1b, S2a, S2b;
    tf2x32(0u, 42u, 0u, 0u, K1a, K1b);
    tf2x32(0u, 42u, 0u, 1u, S1a, S1b);
    tf2x32(K1a, K1b, 0u, 1u, S2a, S2b);

    gen_keys_kernel<<<N_PTS / 256, 256>>>(S1a, S1b);
    run_full_sort();
    extract_val<<<N_PTS / 256, 256>>>();
    gen_keys_kernel<<<N_PTS / 256, 256>>>(S2a, S2b);
    run_full_sort();

    gather_init<<<N_CLU, 256>>>(X);
    convert_x<<<N_PTS, 1024>>>(X);

    for (int it = 0; it < 10; it++) {
        convert_c<<<N_CLU, 1024>>>();
        csq_kernel<<<N_CLU, 256>>>();
        dist_hmma<<<N_PTS / 128, 256>>>();
        refine_assign<<<N_PTS * 32 / 256, 256>>>(X);
        zero_sums<<<(N_CLU * DIM) / 256, 256>>>();
        scatter_add<<<N_PTS, 256>>>(X);
        finalize_cent<<<N_CLU, 256>>>();
    }

    zero_out<<<(NBATCH * N_CLU * DIM) / 1024, 1024>>>(out);
    scatter_out<<<N_PTS, 256>>>(X, out);
    div_out<<<NBATCH * N_CLU, 256>>>(out);
}

// round 8
// speedup vs baseline: 3.7954x; 1.3030x over previous
#include <cuda_runtime.h>
#include <cuda_bf16.h>

typedef unsigned int u32;
typedef unsigned long long u64;

#define N_PTS 32768
#define N_CLU 512
#define DIM   1024
#define NBATCH 16
#define CHUNK 4096
#define EPS   8.0f

// ---------------- scratch (device globals; no allocation) ----------------
__device__ u64 g_sortbuf[N_PTS];
__device__ int g_val[N_PTS];
__device__ __align__(16) float g_cent[N_CLU * DIM];
__device__ float g_csq[N_CLU];
__device__ int g_idx[N_PTS];
__device__ __align__(16) float g_sums[N_CLU * DIM];
__device__ int g_counts[N_CLU];
__device__ int g_counts2[NBATCH * N_CLU];
__device__ __align__(16) float g_dist[N_PTS * N_CLU];   // approx distances

// bf16 copies (X: once per launch, C: written by finalize/gather)
__device__ __align__(128) __nv_bfloat16 g_xb0[N_PTS * DIM];
__device__ __align__(128) __nv_bfloat16 g_cb0[N_CLU * DIM];

__device__ __forceinline__ u32 smem_u32(const void* p) {
    u32 a;
    asm("{ .reg .u64 t; cvta.to.shared.u64 t, %1; cvt.u32.u64 %0, t; }"
        : "=r"(a) : "l"(p));
    return a;
}

#define LDSM4(r, addr) \
    asm volatile("ldmatrix.sync.aligned.m8n8.x4.shared.b16 {%0,%1,%2,%3}, [%4];" \
        : "=r"((r)[0]), "=r"((r)[1]), "=r"((r)[2]), "=r"((r)[3]) : "r"(addr))

#define MMA16816(d, a, b0_, b1_) \
    asm volatile("mma.sync.aligned.m16n8k16.row.col.f32.bf16.bf16.f32 " \
        "{%0,%1,%2,%3}, {%4,%5,%6,%7}, {%8,%9}, {%0,%1,%2,%3};" \
        : "+f"((d)[0]), "+f"((d)[1]), "+f"((d)[2]), "+f"((d)[3]) \
        : "r"((a)[0]), "r"((a)[1]), "r"((a)[2]), "r"((a)[3]), "r"(b0_), "r"(b1_))

// ---------------- Threefry-2x32 (matches jax._src.prng) ----------------
__host__ __device__ inline void tf2x32(u32 k0, u32 k1, u32 x0, u32 x1,
                                       u32& o0, u32& o1) {
    u32 ks2 = k0 ^ k1 ^ 0x1BD11BDAu;
    x0 += k0; x1 += k1;
#define TF_R(r) { x0 += x1; x1 = (x1 << (r)) | (x1 >> (32 - (r))); x1 ^= x0; }
    TF_R(13) TF_R(15) TF_R(26) TF_R(6)
    x0 += k1;  x1 += ks2 + 1u;
    TF_R(17) TF_R(29) TF_R(16) TF_R(24)
    x0 += ks2; x1 += k0 + 2u;
    TF_R(13) TF_R(15) TF_R(26) TF_R(6)
    x0 += k0;  x1 += k1 + 3u;
    TF_R(17) TF_R(29) TF_R(16) TF_R(24)
    x0 += k1;  x1 += ks2 + 4u;
    TF_R(13) TF_R(15) TF_R(26) TF_R(6)
    x0 += ks2; x1 += k0 + 5u;
#undef TF_R
    o0 = x0; o1 = x1;
}

__global__ void gen_keys_kernel(u32 sk0, u32 sk1) {
    int i = blockIdx.x * blockDim.x + threadIdx.x;
    if (i >= N_PTS) return;
    u32 a, b;
    tf2x32(sk0, sk1, 0u, (u32)i, a, b);
    g_sortbuf[i] = ((u64)(a ^ b) << 32) | (u32)i;
}

// ---------------- bitonic sort (stable via (key,pos) composite) ----------------
__global__ void sort_local(void) {
    __shared__ u64 s[CHUNK];
    int base = blockIdx.x * CHUNK;
    for (int t = threadIdx.x; t < CHUNK; t += blockDim.x) s[t] = g_sortbuf[base + t];
    __syncthreads();
    for (int k = 2; k <= CHUNK; k <<= 1) {
        for (int j = k >> 1; j > 0; j >>= 1) {
            for (int t = threadIdx.x; t < CHUNK / 2; t += blockDim.x) {
                int i = ((t & ~(j - 1)) << 1) | (t & (j - 1));
                int l = i | j;
                bool asc = (((base + i) & k) == 0);
                u64 x = s[i], y = s[l];
                if ((x > y) == asc) { s[i] = y; s[l] = x; }
            }
            __syncthreads();
        }
    }
    for (int t = threadIdx.x; t < CHUNK; t += blockDim.x) g_sortbuf[base + t] = s[t];
}

__global__ void sort_global(int k, int j) {
    int t = blockIdx.x * blockDim.x + threadIdx.x;
    int i = ((t & ~(j - 1)) << 1) | (t & (j - 1));
    int l = i | j;
    bool asc = ((i & k) == 0);
    u64 x = g_sortbuf[i], y = g_sortbuf[l];
    if ((x > y) == asc) { g_sortbuf[i] = y; g_sortbuf[l] = x; }
}

__global__ void sort_merge(int k) {
    __shared__ u64 s[CHUNK];
    int base = blockIdx.x * CHUNK;
    bool asc = ((base & k) == 0);
    for (int t = threadIdx.x; t < CHUNK; t += blockDim.x) s[t] = g_sortbuf[base + t];
    __syncthreads();
    for (int j = CHUNK / 2; j > 0; j >>= 1) {
        for (int t = threadIdx.x; t < CHUNK / 2; t += blockDim.x) {
            int i = ((t & ~(j - 1)) << 1) | (t & (j - 1));
            int l = i | j;
            u64 x = s[i], y = s[l];
            if ((x > y) == asc) { s[i] = y; s[l] = x; }
        }
        __syncthreads();
    }
    for (int t = threadIdx.x; t < CHUNK; t += blockDim.x) g_sortbuf[base + t] = s[t];
}

__global__ void extract_val(void) {
    int i = blockIdx.x * blockDim.x + threadIdx.x;
    if (i < N_PTS) g_val[i] = (int)(g_sortbuf[i] & 0xFFFFFFFFu);
}

// gather centroids + write bf16 copy
__global__ void gather_init(const float* __restrict__ X) {
    int c = blockIdx.x;
    int pos = (int)(g_sortbuf[c] & 0xFFFFFFFFu);
    int src = g_val[pos];
    float4 v = ((const float4*)&X[(size_t)src * DIM])[threadIdx.x];
    ((float4*)&g_cent[(size_t)c * DIM])[threadIdx.x] = v;
    __nv_bfloat16* cb = &g_cb0[(size_t)c * DIM + threadIdx.x * 4];
    cb[0] = __float2bfloat16_rn(v.x); cb[1] = __float2bfloat16_rn(v.y);
    cb[2] = __float2bfloat16_rn(v.z); cb[3] = __float2bfloat16_rn(v.w);
}

// bf16 conversion of X (once)
__global__ void convert_x(const float* __restrict__ X) {
    int i = blockIdx.x * blockDim.x + threadIdx.x;
    g_xb0[i] = __float2bfloat16_rn(X[i]);
}

// csq: kept bit-identical to earlier rounds (strided sum + tree reduce)
__global__ void csq_kernel(void) {
    int c = blockIdx.x;
    const float* row = &g_cent[(size_t)c * DIM];
    float s = 0.f;
    for (int t = threadIdx.x; t < DIM; t += 256) { float v = row[t]; s += v * v; }
    __shared__ float red[256];
    red[threadIdx.x] = s; __syncthreads();
    for (int o = 128; o > 0; o >>= 1) {
        if (threadIdx.x < o) red[threadIdx.x] += red[threadIdx.x + o];
        __syncthreads();
    }
    if (threadIdx.x == 0) g_csq[c] = red[0];
}

// ---------------- Phase 1: single bf16 HMMA approx distance matrix ----------------
// CTA: 128 points x 512 clusters (4 col passes of 128). 8 warps.
// K = 1024, chunks of 32, double-buffered smem (stride 40 bf16, conflict-free).
#define SSTR 40
#define NCH 32

__global__ void __launch_bounds__(256) dist_hmma(void) {
    __shared__ __nv_bfloat16 sA[2][128 * SSTR];
    __shared__ __nv_bfloat16 sB[2][128 * SSTR];
    __shared__ float s_csq[N_CLU];

    int tid = threadIdx.x, wid = tid >> 5, lid = tid & 31;
    int row0 = blockIdx.x * 128;
    for (int j = tid; j < N_CLU; j += 256) s_csq[j] = g_csq[j];

    int ar0 = tid >> 2,          as0 = (tid & 3);
    int ar1 = (tid + 256) >> 2,  as1 = ((tid + 256) & 3);

    u32 sAb = smem_u32(sA), sBb = smem_u32(sB);
    int l16 = lid & 15, lh = lid >> 4;
    u32 aoff = (u32)(((wid * 16 + l16) * SSTR + lh * 8) * 2);
    int bm = lid >> 3, bl = lid & 7;
    u32 boff = (u32)(((((bm >> 1) * 8) + bl) * SSTR + (bm & 1) * 8) * 2);

    int erow = lid >> 2;
    int ecol = (lid & 3) * 2;

    for (int nt = 0; nt < 4; nt++) {
        int col0 = nt * 128;
        float acc[16][4];
#pragma unroll
        for (int t = 0; t < 16; t++)
#pragma unroll
            for (int i = 0; i < 4; i++) acc[t][i] = 0.f;

        uint4 ra0, ra1, rb0, rb1;
        {   // prologue: chunk 0
            ra0 = *(const uint4*)(g_xb0 + (size_t)(row0 + ar0) * DIM + as0 * 8);
            ra1 = *(const uint4*)(g_xb0 + (size_t)(row0 + ar1) * DIM + as1 * 8);
            rb0 = *(const uint4*)(g_cb0 + (size_t)(col0 + ar0) * DIM + as0 * 8);
            rb1 = *(const uint4*)(g_cb0 + (size_t)(col0 + ar1) * DIM + as1 * 8);
        }
        *(uint4*)&sA[0][ar0 * SSTR + as0 * 8] = ra0;
        *(uint4*)&sA[0][ar1 * SSTR + as1 * 8] = ra1;
        *(uint4*)&sB[0][ar0 * SSTR + as0 * 8] = rb0;
        *(uint4*)&sB[0][ar1 * SSTR + as1 * 8] = rb1;
        __syncthreads();

        for (int c = 0; c < NCH; c++) {
            int buf = c & 1;
            bool more = (c + 1 < NCH);
            if (more) {
                int kk = (c + 1) << 5;
                ra0 = *(const uint4*)(g_xb0 + (size_t)(row0 + ar0) * DIM + kk + as0 * 8);
                ra1 = *(const uint4*)(g_xb0 + (size_t)(row0 + ar1) * DIM + kk + as1 * 8);
                rb0 = *(const uint4*)(g_cb0 + (size_t)(col0 + ar0) * DIM + kk + as0 * 8);
                rb1 = *(const uint4*)(g_cb0 + (size_t)(col0 + ar1) * DIM + kk + as1 * 8);
            }
            u32 abase = sAb + buf * (128 * SSTR * 2);
            u32 bbase = sBb + buf * (128 * SSTR * 2);
            u32 afr0[4], afr1[4];
            LDSM4(afr0, abase + aoff);
            LDSM4(afr1, abase + aoff + 32);
#pragma unroll
            for (int p = 0; p < 8; p++) {
                u32 bb = bbase + boff + (u32)(p * 16 * SSTR * 2);
                u32 bf[4];
                LDSM4(bf, bb);
                MMA16816(acc[2 * p],     afr0, bf[0], bf[1]);
                MMA16816(acc[2 * p + 1], afr0, bf[2], bf[3]);
                LDSM4(bf, bb + 32);
                MMA16816(acc[2 * p],     afr1, bf[0], bf[1]);
                MMA16816(acc[2 * p + 1], afr1, bf[2], bf[3]);
            }
            if (more) {
                __syncthreads();
                int nb = buf ^ 1;
                *(uint4*)&sA[nb][ar0 * SSTR + as0 * 8] = ra0;
                *(uint4*)&sA[nb][ar1 * SSTR + as1 * 8] = ra1;
                *(uint4*)&sB[nb][ar0 * SSTR + as0 * 8] = rb0;
                *(uint4*)&sB[nb][ar1 * SSTR + as1 * 8] = rb1;
                __syncthreads();
            }
        }
        // store approx distances csq - 2*dot
        {
            int r = row0 + wid * 16 + erow;
#pragma unroll
            for (int t = 0; t < 16; t++) {
                int cbase = col0 + t * 8 + ecol;
                float cs0 = s_csq[cbase], cs1 = s_csq[cbase + 1];
                float2 v0 = make_float2(cs0 - 2.0f * acc[t][0], cs1 - 2.0f * acc[t][1]);
                float2 v1 = make_float2(cs0 - 2.0f * acc[t][2], cs1 - 2.0f * acc[t][3]);
                *(float2*)&g_dist[(size_t)r * N_CLU + cbase] = v0;
                *(float2*)&g_dist[(size_t)(r + 8) * N_CLU + cbase] = v1;
            }
        }
        __syncthreads();
    }
}

// ---------------- Phase 2: exact fp32 rescue + fused scatter ----------------
// One warp per point. X row cached in registers (8 x float4 per lane),
// reused for candidate dots AND the scatter into g_sums.
__global__ void __launch_bounds__(256) refine_scatter(const float* __restrict__ X) {
    int wip = (blockIdx.x * blockDim.x + threadIdx.x) >> 5;
    int lane = threadIdx.x & 31;
    const float* drow = &g_dist[(size_t)wip * N_CLU];
    float d[16];
    float m = 3.4e38f;
#pragma unroll
    for (int k = 0; k < 16; k++) { d[k] = drow[k * 32 + lane]; m = fminf(m, d[k]); }
#pragma unroll
    for (int o = 16; o; o >>= 1) m = fminf(m, __shfl_xor_sync(0xFFFFFFFFu, m, o));
    float thr = m + EPS;

    const float4* xrow4 = (const float4*)&X[(size_t)wip * DIM];
    float4 xr[8];
#pragma unroll
    for (int q = 0; q < 8; q++) xr[q] = xrow4[lane + 32 * q];

    float best = 3.4e38f;
    int bidx = N_CLU;
#pragma unroll 1
    for (int k = 0; k < 16; k++) {
        u32 mask = __ballot_sync(0xFFFFFFFFu, d[k] < thr);
        while (mask) {
            int src = __ffs(mask) - 1;
            mask &= mask - 1;
            int c = k * 32 + src;
            const float4* crow4 = (const float4*)&g_cent[(size_t)c * DIM];
            float s = 0.f;
#pragma unroll
            for (int q = 0; q < 8; q++) {
                float4 cv = crow4[lane + 32 * q];
                s += xr[q].x * cv.x + xr[q].y * cv.y + xr[q].z * cv.z + xr[q].w * cv.w;
            }
#pragma unroll
            for (int o = 16; o; o >>= 1) s += __shfl_xor_sync(0xFFFFFFFFu, s, o);
            float dist = g_csq[c] - 2.0f * s;
            if (dist < best || (dist == best && c < bidx)) { best = dist; bidx = c; }
        }
    }
    // bidx is warp-uniform (all lanes saw identical reduced dists)
    if (lane == 0) g_idx[wip] = bidx;
    float4* dst = (float4*)&g_sums[(size_t)bidx * DIM];
#pragma unroll
    for (int q = 0; q < 8; q++) atomicAdd(&dst[lane + 32 * q], xr[q]);
    if (lane == 0) atomicAdd(&g_counts[bidx], 1);
}

// ---------------- centroid update / output ----------------
__global__ void zero_sums(void) {
    int t = blockIdx.x * blockDim.x + threadIdx.x;
    if (t < N_CLU * DIM) g_sums[t] = 0.f;
    if (t < N_CLU) g_counts[t] = 0;
}

// new centroids + bf16 copy (per-element division kept bit-identical)
__global__ void finalize_cent(void) {
    int c = blockIdx.x;
    int cnt = g_counts[c];
    float fc = (float)cnt;
    int t = threadIdx.x;   // 256 threads x float4
    float4 sv = ((const float4*)&g_sums[(size_t)c * DIM])[t];
    float4 cv;
    if (cnt > 0) { cv.x = sv.x / fc; cv.y = sv.y / fc; cv.z = sv.z / fc; cv.w = sv.w / fc; }
    else cv = make_float4(0.f, 0.f, 0.f, 0.f);
    ((float4*)&g_cent[(size_t)c * DIM])[t] = cv;
    __nv_bfloat16* cb = &g_cb0[(size_t)c * DIM + t * 4];
    cb[0] = __float2bfloat16_rn(cv.x); cb[1] = __float2bfloat16_rn(cv.y);
    cb[2] = __float2bfloat16_rn(cv.z); cb[3] = __float2bfloat16_rn(cv.w);
}

__global__ void zero_out(float* __restrict__ out) {
    int t = blockIdx.x * blockDim.x + threadIdx.x;
    out[t] = 0.f;
    if (t < NBATCH * N_CLU) g_counts2[t] = 0;
}

__global__ void scatter_out(const float* __restrict__ X, float* __restrict__ out) {
    int p = blockIdx.x;
    int b = p >> 11;
    int s = b * N_CLU + g_idx[p];
    const float4* src = (const float4*)&X[(size_t)p * DIM];
    float4* dst = (float4*)&out[(size_t)s * DIM];
    atomicAdd(&dst[threadIdx.x], src[threadIdx.x]);
    if (threadIdx.x == 0) atomicAdd(&g_counts2[s], 1);
}

__global__ void div_out(float* __restrict__ out) {
    int s = blockIdx.x;
    int cnt = g_counts2[s];
    if (cnt <= 0) return;
    float fc = (float)cnt;
    for (int k = threadIdx.x; k < DIM; k += 256)
        out[(size_t)s * DIM + k] /= fc;
}

// ---------------- driver ----------------
static void run_full_sort() {
    sort_local<<<N_PTS / CHUNK, 512>>>();
    for (int k = 2 * CHUNK; k <= N_PTS; k <<= 1) {
        for (int j = k >> 1; j >= CHUNK; j >>= 1)
            sort_global<<<N_PTS / 2 / 256, 256>>>(k, j);
        sort_merge<<<N_PTS / CHUNK, 512>>>(k);
    }
}

extern "C" void kernel_launch(void* const* d_in, const int* in_sizes, int n_in,
                              void* d_out, int out_size) {
    (void)in_sizes; (void)n_in; (void)out_size;
    const float* X = (const float*)d_in[0];
    float* out = (float*)d_out;

    // jax.random.key(42): partitionable threefry shuffle, 2 rounds
    u32 K1a, K1b, S1a, S1b, S2a, S2b;
    tf2x32(0u, 42u, 0u, 0u, K1a, K1b);
    tf2x32(0u, 42u, 0u, 1u, S1a, S1b);
    tf2x32(K1a, K1b, 0u, 1u, S2a, S2b);

    gen_keys_kernel<<<N_PTS / 256, 256>>>(S1a, S1b);
    run_full_sort();
    extract_val<<<N_PTS / 256, 256>>>();
    gen_keys_kernel<<<N_PTS / 256, 256>>>(S2a, S2b);
    run_full_sort();

    gather_init<<<N_CLU, 256>>>(X);
    convert_x<<<N_PTS, 1024>>>(X);

    for (int it = 0; it < 10; it++) {
        csq_kernel<<<N_CLU, 256>>>();
        dist_hmma<<<N_PTS / 128, 256>>>();
        zero_sums<<<(N_CLU * DIM) / 256, 256>>>();
        refine_scatter<<<N_PTS * 32 / 256, 256>>>(X);
        finalize_cent<<<N_CLU, 256>>>();
    }

    zero_out<<<(NBATCH * N_CLU * DIM) / 1024, 1024>>>(out);
    scatter_out<<<N_PTS, 256>>>(X, out);
    div_out<<<NBATCH * N_CLU, 256>>>(out);
}